// round 11
// baseline (speedup 1.0000x reference)
#include <cuda_runtime.h>
#include <math.h>

#define B_ 16
#define L_ 2048
#define D_ 768
#define K_ 32
#define D4_ (D_ / 4)           // 192 float4 per row
#define CHUNK_ 32              // tokens per fused block
#define NCHUNK_ (L_ / CHUNK_)  // 64

// scratch (allowed: __device__ global, no allocation)
__device__ float g_denom[B_ * K_];

// ---------------------------------------------------------------------------
// Kernel 0: zero H region of out + g_denom. One float4 store per thread,
// exactly total4 = 98304 threads = 384 blocks x 256.
// ---------------------------------------------------------------------------
__global__ __launch_bounds__(256)
void zero_kernel(float* __restrict__ out) {
    int gtid = blockIdx.x * 256 + threadIdx.x;
    reinterpret_cast<float4*>(out)[gtid] = make_float4(0.f, 0.f, 0.f, 0.f);
    if (gtid < B_ * K_) g_denom[gtid] = 0.0f;
}

// ---------------------------------------------------------------------------
// Fused kernel: one DRAM read of token_hidden.
// grid = (NCHUNK_, B_) = 1024 blocks, 256 threads.
// Phase 0: span id per token (binary search, smem tables).
// Phase 1 (8 warps, 4 tokens/warp interleaved, 24 LDG.128 in flight/warp):
//          dot with w_pool (smem) -> wgt[t] = exp(score), denom atomics.
//          This is the DRAM-streaming phase.
// Phase 2 (tid<192): run-wise 8-unroll accumulate of wgt[t]*row (hits L1),
//          atomicAdd unnormalized sums into out.
// ---------------------------------------------------------------------------
__global__ __launch_bounds__(256)
void fused_kernel(const float* __restrict__ hid,
                  const float* __restrict__ amask,
                  const int* __restrict__ starts,
                  const int* __restrict__ ends,
                  const float* __restrict__ w,
                  const float* __restrict__ bias,
                  float* __restrict__ out) {
    const int c = blockIdx.x;           // chunk
    const int b = blockIdx.y;           // batch
    const int tid = threadIdx.x;
    const int wid = tid >> 5;           // 0..7
    const int lane = tid & 31;

    __shared__ float4 wsh[D4_];         // 3 KB
    __shared__ int   s_start[K_];
    __shared__ int   s_end[K_];
    __shared__ int   sid[CHUNK_];
    __shared__ float wgt[CHUNK_];

    if (tid < D4_)
        wsh[tid] = reinterpret_cast<const float4*>(w)[tid];
    if (tid < K_) {
        s_start[tid] = starts[b * K_ + tid];
        s_end[tid]   = ends[b * K_ + tid];
    }
    __syncthreads();

    const int base = c * CHUNK_;
    const float* am = amask + b * L_;
    const float4* hb = reinterpret_cast<const float4*>(
        hid + ((size_t)b * L_ + base) * D_);

    // ---- phase 0: span id per token ----
    if (tid < CHUNK_) {
        int l = base + tid;
        int lo = 0, hi = K_;
        while (lo < hi) {
            int mid = (lo + hi) >> 1;
            if (s_end[mid] > l) hi = mid; else lo = mid + 1;
        }
        sid[tid] = (lo < K_ && s_start[lo] <= l) ? lo : -1;
    }
    __syncthreads();

    // ---- phase 1: 4 tokens per warp, interleaved dots ----
    const float bias0 = bias[0];
    {
        float acc[4] = {0.0f, 0.0f, 0.0f, 0.0f};
        #pragma unroll
        for (int t4 = 0; t4 < 4; t4++) {
            const int t = wid + t4 * 8;
            if (sid[t] >= 0) {          // warp-uniform branch
                const float4* row = hb + (size_t)t * D4_;
                #pragma unroll
                for (int i = 0; i < 6; i++) {
                    float4 h = row[lane + i * 32];
                    float4 ww = wsh[lane + i * 32];
                    acc[t4] += h.x * ww.x + h.y * ww.y
                             + h.z * ww.z + h.w * ww.w;
                }
            }
        }
        #pragma unroll
        for (int off = 16; off > 0; off >>= 1) {
            #pragma unroll
            for (int t4 = 0; t4 < 4; t4++)
                acc[t4] += __shfl_xor_sync(0xFFFFFFFFu, acc[t4], off);
        }
        if (lane < 4) {
            const int t = wid + lane * 8;
            const int span = sid[t];
            float e = 0.0f;
            if (span >= 0 && am[base + t] >= 0.5f)
                e = expf(acc[lane] + bias0);
            wgt[t] = e;
            if (e > 0.0f) atomicAdd(&g_denom[b * K_ + span], e);
        }
    }
    __syncthreads();

    // ---- phase 2: run-wise unnormalized accumulation (tid < 192) ----
    if (tid < 192) {
        int i = 0;
        while (i < CHUNK_) {
            int span = sid[i];
            int j = i + 1;
            while (j < CHUNK_ && sid[j] == span) j++;
            if (span >= 0) {
                float4 a0 = make_float4(0.f, 0.f, 0.f, 0.f);
                float4 a1 = make_float4(0.f, 0.f, 0.f, 0.f);
                float4 a2 = make_float4(0.f, 0.f, 0.f, 0.f);
                float4 a3 = make_float4(0.f, 0.f, 0.f, 0.f);
                int t = i;
                for (; t + 8 <= j; t += 8) {
                    float w0 = wgt[t],     w1 = wgt[t + 1], w2 = wgt[t + 2], w3 = wgt[t + 3];
                    float w4 = wgt[t + 4], w5 = wgt[t + 5], w6 = wgt[t + 6], w7 = wgt[t + 7];
                    float4 h0 = hb[(size_t)(t)     * D4_ + tid];
                    float4 h1 = hb[(size_t)(t + 1) * D4_ + tid];
                    float4 h2 = hb[(size_t)(t + 2) * D4_ + tid];
                    float4 h3 = hb[(size_t)(t + 3) * D4_ + tid];
                    float4 h4 = hb[(size_t)(t + 4) * D4_ + tid];
                    float4 h5 = hb[(size_t)(t + 5) * D4_ + tid];
                    float4 h6 = hb[(size_t)(t + 6) * D4_ + tid];
                    float4 h7 = hb[(size_t)(t + 7) * D4_ + tid];
                    a0.x += w0 * h0.x; a0.y += w0 * h0.y; a0.z += w0 * h0.z; a0.w += w0 * h0.w;
                    a1.x += w1 * h1.x; a1.y += w1 * h1.y; a1.z += w1 * h1.z; a1.w += w1 * h1.w;
                    a2.x += w2 * h2.x; a2.y += w2 * h2.y; a2.z += w2 * h2.z; a2.w += w2 * h2.w;
                    a3.x += w3 * h3.x; a3.y += w3 * h3.y; a3.z += w3 * h3.z; a3.w += w3 * h3.w;
                    a0.x += w4 * h4.x; a0.y += w4 * h4.y; a0.z += w4 * h4.z; a0.w += w4 * h4.w;
                    a1.x += w5 * h5.x; a1.y += w5 * h5.y; a1.z += w5 * h5.z; a1.w += w5 * h5.w;
                    a2.x += w6 * h6.x; a2.y += w6 * h6.y; a2.z += w6 * h6.z; a2.w += w6 * h6.w;
                    a3.x += w7 * h7.x; a3.y += w7 * h7.y; a3.z += w7 * h7.z; a3.w += w7 * h7.w;
                }
                for (; t + 4 <= j; t += 4) {
                    float w0 = wgt[t], w1 = wgt[t + 1], w2 = wgt[t + 2], w3 = wgt[t + 3];
                    float4 h0 = hb[(size_t)(t)     * D4_ + tid];
                    float4 h1 = hb[(size_t)(t + 1) * D4_ + tid];
                    float4 h2 = hb[(size_t)(t + 2) * D4_ + tid];
                    float4 h3 = hb[(size_t)(t + 3) * D4_ + tid];
                    a0.x += w0 * h0.x; a0.y += w0 * h0.y; a0.z += w0 * h0.z; a0.w += w0 * h0.w;
                    a1.x += w1 * h1.x; a1.y += w1 * h1.y; a1.z += w1 * h1.z; a1.w += w1 * h1.w;
                    a2.x += w2 * h2.x; a2.y += w2 * h2.y; a2.z += w2 * h2.z; a2.w += w2 * h2.w;
                    a3.x += w3 * h3.x; a3.y += w3 * h3.y; a3.z += w3 * h3.z; a3.w += w3 * h3.w;
                }
                for (; t < j; t++) {
                    float w0 = wgt[t];
                    float4 h0 = hb[(size_t)t * D4_ + tid];
                    a0.x += w0 * h0.x; a0.y += w0 * h0.y; a0.z += w0 * h0.z; a0.w += w0 * h0.w;
                }
                float rx = a0.x + a1.x + a2.x + a3.x;
                float ry = a0.y + a1.y + a2.y + a3.y;
                float rz = a0.z + a1.z + a2.z + a3.z;
                float rw = a0.w + a1.w + a2.w + a3.w;
                float* Hrow = out + ((size_t)(b * K_ + span)) * D_ + 4 * tid;
                atomicAdd(Hrow + 0, rx);
                atomicAdd(Hrow + 1, ry);
                atomicAdd(Hrow + 2, rz);
                atomicAdd(Hrow + 3, rw);
            }
            i = j;
        }
    }
}

// ---------------------------------------------------------------------------
// Kernel 2: normalize out by denom, write sent_mask.
// grid (K_, B_), 192 threads: one block per (b,k) row.
// ---------------------------------------------------------------------------
__global__ __launch_bounds__(192)
void scale_kernel(float* __restrict__ out) {
    const int k = blockIdx.x;
    const int b = blockIdx.y;
    const int tid = threadIdx.x;
    const int bk = b * K_ + k;

    float d = g_denom[bk];
    float inv = (d > 0.0f) ? (1.0f / d) : 0.0f;

    float4* H4 = reinterpret_cast<float4*>(out + (size_t)bk * D_);
    float4 v = H4[tid];
    v.x *= inv; v.y *= inv; v.z *= inv; v.w *= inv;
    H4[tid] = v;

    if (tid == 0)
        out[(size_t)B_ * K_ * D_ + bk] = (d > 0.0f) ? 1.0f : 0.0f;
}

// ---------------------------------------------------------------------------
extern "C" void kernel_launch(void* const* d_in, const int* in_sizes, int n_in,
                              void* d_out, int out_size) {
    const float* token_hidden   = (const float*)d_in[0];
    const float* attention_mask = (const float*)d_in[1];
    const int*   span_starts    = (const int*)d_in[2];
    const int*   span_ends      = (const int*)d_in[3];
    const float* w_pool         = (const float*)d_in[4];
    const float* b_pool         = (const float*)d_in[5];
    float* out = (float*)d_out;

    // zero: exactly one float4 per thread (B*K*D/4 = 98304 = 384*256)
    zero_kernel<<<384, 256>>>(out);

    dim3 gridF(NCHUNK_, B_);
    fused_kernel<<<gridF, 256>>>(token_hidden, attention_mask,
                                 span_starts, span_ends,
                                 w_pool, b_pool, out);

    dim3 gridS(K_, B_);
    scale_kernel<<<gridS, 192>>>(out);
}

// round 12
// speedup vs baseline: 1.0240x; 1.0240x over previous
#include <cuda_runtime.h>
#include <math.h>

#define B_ 16
#define L_ 2048
#define D_ 768
#define K_ 32
#define D4_ (D_ / 4)           // 192 float4 per row
#define CHUNK_ 32              // tokens per fused block
#define NCHUNK_ (L_ / CHUNK_)  // 64

// Persistent scratch (zero-initialized at load; scale_kernel re-zeroes the
// parts it consumes every call, so each kernel_launch sees clean state).
__device__ float g_H[B_ * K_ * D_];
__device__ float g_denom[B_ * K_];

// ---------------------------------------------------------------------------
// Fused kernel: one DRAM read of token_hidden.
// grid = (NCHUNK_, B_) = 1024 blocks, 192 threads.
// Phase 0: span id per token (binary search, smem tables).
// Phase 1: warp-per-token dot with w_pool (smem) -> wgt[t] = exp(score),
//          token atomicAdd into g_denom[span]. Rows enter L1/L2 here.
// Phase 2: run-wise 8-unroll accumulate of wgt[t]*row (re-read hits L1/L2),
//          atomicAdd unnormalized sums into g_H.
// ---------------------------------------------------------------------------
__global__ __launch_bounds__(192)
void fused_kernel(const float* __restrict__ hid,
                  const float* __restrict__ amask,
                  const int* __restrict__ starts,
                  const int* __restrict__ ends,
                  const float* __restrict__ w,
                  const float* __restrict__ bias) {
    const int c = blockIdx.x;           // chunk
    const int b = blockIdx.y;           // batch
    const int tid = threadIdx.x;
    const int wid = tid >> 5;           // 0..5
    const int lane = tid & 31;

    __shared__ float4 wsh[D4_];         // 3 KB, D4_ == 192 == blockDim
    __shared__ int   s_start[K_];
    __shared__ int   s_end[K_];
    __shared__ int   sid[CHUNK_];
    __shared__ float wgt[CHUNK_];

    wsh[tid] = reinterpret_cast<const float4*>(w)[tid];
    if (tid < K_) {
        s_start[tid] = starts[b * K_ + tid];
        s_end[tid]   = ends[b * K_ + tid];
    }
    __syncthreads();

    const int base = c * CHUNK_;
    const float* am = amask + b * L_;
    const float4* hb = reinterpret_cast<const float4*>(
        hid + ((size_t)b * L_ + base) * D_);

    // ---- phase 0: span id per token ----
    if (tid < CHUNK_) {
        int l = base + tid;
        int lo = 0, hi = K_;
        while (lo < hi) {
            int mid = (lo + hi) >> 1;
            if (s_end[mid] > l) hi = mid; else lo = mid + 1;
        }
        sid[tid] = (lo < K_ && s_start[lo] <= l) ? lo : -1;
    }
    __syncthreads();

    // ---- phase 1: scores + exp weights + denom atomics ----
    const float bias0 = bias[0];
    for (int t = wid; t < CHUNK_; t += 6) {
        int span = sid[t];
        if (span < 0) { if (lane == 0) wgt[t] = 0.0f; continue; }
        const float4* row = hb + (size_t)t * D4_;
        float acc = 0.0f;
        #pragma unroll
        for (int i = 0; i < 6; i++) {
            float4 h = row[lane + i * 32];
            float4 ww = wsh[lane + i * 32];
            acc += h.x * ww.x + h.y * ww.y + h.z * ww.z + h.w * ww.w;
        }
        #pragma unroll
        for (int off = 16; off > 0; off >>= 1)
            acc += __shfl_xor_sync(0xFFFFFFFFu, acc, off);
        if (lane == 0) {
            float e = (am[base + t] >= 0.5f) ? expf(acc + bias0) : 0.0f;
            wgt[t] = e;
            if (e > 0.0f) atomicAdd(&g_denom[b * K_ + span], e);
        }
    }
    __syncthreads();

    // ---- phase 2: run-wise unnormalized accumulation ----
    int i = 0;
    while (i < CHUNK_) {
        int span = sid[i];
        int j = i + 1;
        while (j < CHUNK_ && sid[j] == span) j++;
        if (span >= 0) {
            float4 a0 = make_float4(0.f, 0.f, 0.f, 0.f);
            float4 a1 = make_float4(0.f, 0.f, 0.f, 0.f);
            float4 a2 = make_float4(0.f, 0.f, 0.f, 0.f);
            float4 a3 = make_float4(0.f, 0.f, 0.f, 0.f);
            int t = i;
            for (; t + 8 <= j; t += 8) {
                float w0 = wgt[t],     w1 = wgt[t + 1], w2 = wgt[t + 2], w3 = wgt[t + 3];
                float w4 = wgt[t + 4], w5 = wgt[t + 5], w6 = wgt[t + 6], w7 = wgt[t + 7];
                float4 h0 = hb[(size_t)(t)     * D4_ + tid];
                float4 h1 = hb[(size_t)(t + 1) * D4_ + tid];
                float4 h2 = hb[(size_t)(t + 2) * D4_ + tid];
                float4 h3 = hb[(size_t)(t + 3) * D4_ + tid];
                float4 h4 = hb[(size_t)(t + 4) * D4_ + tid];
                float4 h5 = hb[(size_t)(t + 5) * D4_ + tid];
                float4 h6 = hb[(size_t)(t + 6) * D4_ + tid];
                float4 h7 = hb[(size_t)(t + 7) * D4_ + tid];
                a0.x += w0 * h0.x; a0.y += w0 * h0.y; a0.z += w0 * h0.z; a0.w += w0 * h0.w;
                a1.x += w1 * h1.x; a1.y += w1 * h1.y; a1.z += w1 * h1.z; a1.w += w1 * h1.w;
                a2.x += w2 * h2.x; a2.y += w2 * h2.y; a2.z += w2 * h2.z; a2.w += w2 * h2.w;
                a3.x += w3 * h3.x; a3.y += w3 * h3.y; a3.z += w3 * h3.z; a3.w += w3 * h3.w;
                a0.x += w4 * h4.x; a0.y += w4 * h4.y; a0.z += w4 * h4.z; a0.w += w4 * h4.w;
                a1.x += w5 * h5.x; a1.y += w5 * h5.y; a1.z += w5 * h5.z; a1.w += w5 * h5.w;
                a2.x += w6 * h6.x; a2.y += w6 * h6.y; a2.z += w6 * h6.z; a2.w += w6 * h6.w;
                a3.x += w7 * h7.x; a3.y += w7 * h7.y; a3.z += w7 * h7.z; a3.w += w7 * h7.w;
            }
            for (; t + 4 <= j; t += 4) {
                float w0 = wgt[t], w1 = wgt[t + 1], w2 = wgt[t + 2], w3 = wgt[t + 3];
                float4 h0 = hb[(size_t)(t)     * D4_ + tid];
                float4 h1 = hb[(size_t)(t + 1) * D4_ + tid];
                float4 h2 = hb[(size_t)(t + 2) * D4_ + tid];
                float4 h3 = hb[(size_t)(t + 3) * D4_ + tid];
                a0.x += w0 * h0.x; a0.y += w0 * h0.y; a0.z += w0 * h0.z; a0.w += w0 * h0.w;
                a1.x += w1 * h1.x; a1.y += w1 * h1.y; a1.z += w1 * h1.z; a1.w += w1 * h1.w;
                a2.x += w2 * h2.x; a2.y += w2 * h2.y; a2.z += w2 * h2.z; a2.w += w2 * h2.w;
                a3.x += w3 * h3.x; a3.y += w3 * h3.y; a3.z += w3 * h3.z; a3.w += w3 * h3.w;
            }
            for (; t < j; t++) {
                float w0 = wgt[t];
                float4 h0 = hb[(size_t)t * D4_ + tid];
                a0.x += w0 * h0.x; a0.y += w0 * h0.y; a0.z += w0 * h0.z; a0.w += w0 * h0.w;
            }
            float rx = a0.x + a1.x + a2.x + a3.x;
            float ry = a0.y + a1.y + a2.y + a3.y;
            float rz = a0.z + a1.z + a2.z + a3.z;
            float rw = a0.w + a1.w + a2.w + a3.w;
            float* Hrow = g_H + ((size_t)(b * K_ + span)) * D_ + 4 * tid;
            atomicAdd(Hrow + 0, rx);
            atomicAdd(Hrow + 1, ry);
            atomicAdd(Hrow + 2, rz);
            atomicAdd(Hrow + 3, rw);
        }
        i = j;
    }
}

// ---------------------------------------------------------------------------
// Kernel 2: normalize g_H by denom into out, write sent_mask, then RE-ZERO
// the scratch this block consumed (self-cleaning for the next call).
// grid (K_, B_), 192 threads: one block per (b,k) row.
// ---------------------------------------------------------------------------
__global__ __launch_bounds__(192)
void scale_kernel(float* __restrict__ out) {
    const int k = blockIdx.x;
    const int b = blockIdx.y;
    const int tid = threadIdx.x;
    const int bk = b * K_ + k;

    float d = g_denom[bk];
    float inv = (d > 0.0f) ? (1.0f / d) : 0.0f;

    float4* src4 = reinterpret_cast<float4*>(g_H + (size_t)bk * D_);
    float4* dst4 = reinterpret_cast<float4*>(out + (size_t)bk * D_);

    float4 v = src4[tid];
    v.x *= inv; v.y *= inv; v.z *= inv; v.w *= inv;
    dst4[tid] = v;
    src4[tid] = make_float4(0.0f, 0.0f, 0.0f, 0.0f);   // clean for next call

    if (tid == 0) {
        out[(size_t)B_ * K_ * D_ + bk] = (d > 0.0f) ? 1.0f : 0.0f;
        g_denom[bk] = 0.0f;                             // clean for next call
    }
}

// ---------------------------------------------------------------------------
extern "C" void kernel_launch(void* const* d_in, const int* in_sizes, int n_in,
                              void* d_out, int out_size) {
    const float* token_hidden   = (const float*)d_in[0];
    const float* attention_mask = (const float*)d_in[1];
    const int*   span_starts    = (const int*)d_in[2];
    const int*   span_ends      = (const int*)d_in[3];
    const float* w_pool         = (const float*)d_in[4];
    const float* b_pool         = (const float*)d_in[5];
    float* out = (float*)d_out;

    dim3 gridF(NCHUNK_, B_);
    fused_kernel<<<gridF, 192>>>(token_hidden, attention_mask,
                                 span_starts, span_ends,
                                 w_pool, b_pool);

    dim3 gridS(K_, B_);
    scale_kernel<<<gridS, 192>>>(out);
}

// round 14
// speedup vs baseline: 1.0685x; 1.0435x over previous
#include <cuda_runtime.h>
#include <math.h>

#define B_ 16
#define L_ 2048
#define D_ 768
#define K_ 32
#define D4_ (D_ / 4)           // 192 float4 per row
#define CHUNK_ 32              // tokens per fused block
#define NCHUNK_ (L_ / CHUNK_)  // 64

// Persistent scratch (zero-initialized at load; scale_kernel re-zeroes the
// parts it consumes every call, so each kernel_launch sees clean state).
__device__ float g_H[B_ * K_ * D_];
__device__ float g_denom[B_ * K_];

// ---------------------------------------------------------------------------
// Fused kernel: one DRAM read of token_hidden.
// grid = (NCHUNK_, B_) = 1024 blocks, 192 threads.
// Phase 0: span id per token (binary search, smem tables).
// Phase 1: warp-per-token dot with w_pool (smem) -> wgt[t] = exp(score),
//          token atomicAdd into g_denom[span].
// Phase 2: run-wise 8-unroll accumulate of wgt[t]*row (hits L1/L2),
//          atomicAdd unnormalized sums into g_H.
// Issues griddepcontrol.launch_dependents early so the PDL-attached
// scale_kernel can pre-launch and hide its setup latency.
// ---------------------------------------------------------------------------
__global__ __launch_bounds__(192)
void fused_kernel(const float* __restrict__ hid,
                  const float* __restrict__ amask,
                  const int* __restrict__ starts,
                  const int* __restrict__ ends,
                  const float* __restrict__ w,
                  const float* __restrict__ bias) {
    const int c = blockIdx.x;           // chunk
    const int b = blockIdx.y;           // batch
    const int tid = threadIdx.x;
    const int wid = tid >> 5;           // 0..5
    const int lane = tid & 31;

    __shared__ float4 wsh[D4_];         // 3 KB, D4_ == 192 == blockDim
    __shared__ int   s_start[K_];
    __shared__ int   s_end[K_];
    __shared__ int   sid[CHUNK_];
    __shared__ float wgt[CHUNK_];

    wsh[tid] = reinterpret_cast<const float4*>(w)[tid];
    if (tid < K_) {
        s_start[tid] = starts[b * K_ + tid];
        s_end[tid]   = ends[b * K_ + tid];
    }
    __syncthreads();

    // let the dependent scale_kernel start scheduling its blocks now;
    // its griddepcontrol.wait still enforces full memory visibility.
    asm volatile("griddepcontrol.launch_dependents;" ::: "memory");

    const int base = c * CHUNK_;
    const float* am = amask + b * L_;
    const float4* hb = reinterpret_cast<const float4*>(
        hid + ((size_t)b * L_ + base) * D_);

    // ---- phase 0: span id per token ----
    if (tid < CHUNK_) {
        int l = base + tid;
        int lo = 0, hi = K_;
        while (lo < hi) {
            int mid = (lo + hi) >> 1;
            if (s_end[mid] > l) hi = mid; else lo = mid + 1;
        }
        sid[tid] = (lo < K_ && s_start[lo] <= l) ? lo : -1;
    }
    __syncthreads();

    // ---- phase 1: scores + exp weights + denom atomics ----
    const float bias0 = bias[0];
    for (int t = wid; t < CHUNK_; t += 6) {
        int span = sid[t];
        if (span < 0) { if (lane == 0) wgt[t] = 0.0f; continue; }
        const float4* row = hb + (size_t)t * D4_;
        float acc = 0.0f;
        #pragma unroll
        for (int i = 0; i < 6; i++) {
            float4 h = row[lane + i * 32];
            float4 ww = wsh[lane + i * 32];
            acc += h.x * ww.x + h.y * ww.y + h.z * ww.z + h.w * ww.w;
        }
        #pragma unroll
        for (int off = 16; off > 0; off >>= 1)
            acc += __shfl_xor_sync(0xFFFFFFFFu, acc, off);
        if (lane == 0) {
            float e = (am[base + t] >= 0.5f) ? expf(acc + bias0) : 0.0f;
            wgt[t] = e;
            if (e > 0.0f) atomicAdd(&g_denom[b * K_ + span], e);
        }
    }
    __syncthreads();

    // ---- phase 2: run-wise unnormalized accumulation ----
    int i = 0;
    while (i < CHUNK_) {
        int span = sid[i];
        int j = i + 1;
        while (j < CHUNK_ && sid[j] == span) j++;
        if (span >= 0) {
            float4 a0 = make_float4(0.f, 0.f, 0.f, 0.f);
            float4 a1 = make_float4(0.f, 0.f, 0.f, 0.f);
            float4 a2 = make_float4(0.f, 0.f, 0.f, 0.f);
            float4 a3 = make_float4(0.f, 0.f, 0.f, 0.f);
            int t = i;
            for (; t + 8 <= j; t += 8) {
                float w0 = wgt[t],     w1 = wgt[t + 1], w2 = wgt[t + 2], w3 = wgt[t + 3];
                float w4 = wgt[t + 4], w5 = wgt[t + 5], w6 = wgt[t + 6], w7 = wgt[t + 7];
                float4 h0 = hb[(size_t)(t)     * D4_ + tid];
                float4 h1 = hb[(size_t)(t + 1) * D4_ + tid];
                float4 h2 = hb[(size_t)(t + 2) * D4_ + tid];
                float4 h3 = hb[(size_t)(t + 3) * D4_ + tid];
                float4 h4 = hb[(size_t)(t + 4) * D4_ + tid];
                float4 h5 = hb[(size_t)(t + 5) * D4_ + tid];
                float4 h6 = hb[(size_t)(t + 6) * D4_ + tid];
                float4 h7 = hb[(size_t)(t + 7) * D4_ + tid];
                a0.x += w0 * h0.x; a0.y += w0 * h0.y; a0.z += w0 * h0.z; a0.w += w0 * h0.w;
                a1.x += w1 * h1.x; a1.y += w1 * h1.y; a1.z += w1 * h1.z; a1.w += w1 * h1.w;
                a2.x += w2 * h2.x; a2.y += w2 * h2.y; a2.z += w2 * h2.z; a2.w += w2 * h2.w;
                a3.x += w3 * h3.x; a3.y += w3 * h3.y; a3.z += w3 * h3.z; a3.w += w3 * h3.w;
                a0.x += w4 * h4.x; a0.y += w4 * h4.y; a0.z += w4 * h4.z; a0.w += w4 * h4.w;
                a1.x += w5 * h5.x; a1.y += w5 * h5.y; a1.z += w5 * h5.z; a1.w += w5 * h5.w;
                a2.x += w6 * h6.x; a2.y += w6 * h6.y; a2.z += w6 * h6.z; a2.w += w6 * h6.w;
                a3.x += w7 * h7.x; a3.y += w7 * h7.y; a3.z += w7 * h7.z; a3.w += w7 * h7.w;
            }
            for (; t + 4 <= j; t += 4) {
                float w0 = wgt[t], w1 = wgt[t + 1], w2 = wgt[t + 2], w3 = wgt[t + 3];
                float4 h0 = hb[(size_t)(t)     * D4_ + tid];
                float4 h1 = hb[(size_t)(t + 1) * D4_ + tid];
                float4 h2 = hb[(size_t)(t + 2) * D4_ + tid];
                float4 h3 = hb[(size_t)(t + 3) * D4_ + tid];
                a0.x += w0 * h0.x; a0.y += w0 * h0.y; a0.z += w0 * h0.z; a0.w += w0 * h0.w;
                a1.x += w1 * h1.x; a1.y += w1 * h1.y; a1.z += w1 * h1.z; a1.w += w1 * h1.w;
                a2.x += w2 * h2.x; a2.y += w2 * h2.y; a2.z += w2 * h2.z; a2.w += w2 * h2.w;
                a3.x += w3 * h3.x; a3.y += w3 * h3.y; a3.z += w3 * h3.z; a3.w += w3 * h3.w;
            }
            for (; t < j; t++) {
                float w0 = wgt[t];
                float4 h0 = hb[(size_t)t * D4_ + tid];
                a0.x += w0 * h0.x; a0.y += w0 * h0.y; a0.z += w0 * h0.z; a0.w += w0 * h0.w;
            }
            float rx = a0.x + a1.x + a2.x + a3.x;
            float ry = a0.y + a1.y + a2.y + a3.y;
            float rz = a0.z + a1.z + a2.z + a3.z;
            float rw = a0.w + a1.w + a2.w + a3.w;
            float* Hrow = g_H + ((size_t)(b * K_ + span)) * D_ + 4 * tid;
            atomicAdd(Hrow + 0, rx);
            atomicAdd(Hrow + 1, ry);
            atomicAdd(Hrow + 2, rz);
            atomicAdd(Hrow + 3, rw);
        }
        i = j;
    }
}

// ---------------------------------------------------------------------------
// Kernel 2 (PDL dependent): wait for fused grid's memory, then normalize
// g_H by denom into out, write sent_mask, and RE-ZERO consumed scratch.
// grid (K_, B_), 192 threads: one block per (b,k) row.
// ---------------------------------------------------------------------------
__global__ __launch_bounds__(192)
void scale_kernel(float* __restrict__ out) {
    // blocks may be resident before fused finishes; this waits until all
    // upstream memory operations are visible.
    asm volatile("griddepcontrol.wait;" ::: "memory");

    const int k = blockIdx.x;
    const int b = blockIdx.y;
    const int tid = threadIdx.x;
    const int bk = b * K_ + k;

    float d = g_denom[bk];
    float inv = (d > 0.0f) ? (1.0f / d) : 0.0f;

    float4* src4 = reinterpret_cast<float4*>(g_H + (size_t)bk * D_);
    float4* dst4 = reinterpret_cast<float4*>(out + (size_t)bk * D_);

    float4 v = src4[tid];
    v.x *= inv; v.y *= inv; v.z *= inv; v.w *= inv;
    dst4[tid] = v;
    src4[tid] = make_float4(0.0f, 0.0f, 0.0f, 0.0f);   // clean for next call

    if (tid == 0) {
        out[(size_t)B_ * K_ * D_ + bk] = (d > 0.0f) ? 1.0f : 0.0f;
        g_denom[bk] = 0.0f;                             // clean for next call
    }
}

// ---------------------------------------------------------------------------
extern "C" void kernel_launch(void* const* d_in, const int* in_sizes, int n_in,
                              void* d_out, int out_size) {
    const float* token_hidden   = (const float*)d_in[0];
    const float* attention_mask = (const float*)d_in[1];
    const int*   span_starts    = (const int*)d_in[2];
    const int*   span_ends      = (const int*)d_in[3];
    const float* w_pool         = (const float*)d_in[4];
    const float* b_pool         = (const float*)d_in[5];
    float* out = (float*)d_out;

    dim3 gridF(NCHUNK_, B_);
    fused_kernel<<<gridF, 192>>>(token_hidden, attention_mask,
                                 span_starts, span_ends,
                                 w_pool, b_pool);

    // scale_kernel attached via Programmatic Dependent Launch: it may begin
    // scheduling while fused_kernel runs; griddepcontrol.wait enforces the
    // data dependency.
    cudaLaunchConfig_t cfg = {};
    cfg.gridDim  = dim3(K_, B_);
    cfg.blockDim = dim3(192);
    cfg.dynamicSmemBytes = 0;
    cfg.stream = 0;
    cudaLaunchAttribute attrs[1];
    attrs[0].id = cudaLaunchAttributeProgrammaticStreamSerialization;
    attrs[0].val.programmaticStreamSerializationAllowed = 1;
    cfg.attrs = attrs;
    cfg.numAttrs = 1;
    cudaLaunchKernelEx(&cfg, scale_kernel, out);
}